// round 6
// baseline (speedup 1.0000x reference)
#include <cuda_runtime.h>
#include <cstdint>

// Problem constants
#define BB 8
#define NN 2048
#define IND 128
#define OUTD 64
#define NEG_SLOPE 0.2f
#define LOG2E 1.4426950408889634f

// Scratch (device globals: no allocation allowed)
__device__ float g_hp[BB * NN * OUTD];   // projected features (4 MB)
__device__ float g_s[BB * NN];           // (hp @ a_src + b_attn) * log2e
__device__ float g_d[BB * NN];           // (hp @ a_dst) * log2e
__device__ float g_dmax[BB];             // per-batch max of prescaled d

// ---------- packed f32x2 helpers ----------
__device__ __forceinline__ unsigned long long fma2(unsigned long long a,
                                                   unsigned long long b,
                                                   unsigned long long c) {
    unsigned long long d;
    asm("fma.rn.f32x2 %0, %1, %2, %3;" : "=l"(d) : "l"(a), "l"(b), "l"(c));
    return d;
}
__device__ __forceinline__ unsigned long long pk2(float a, float b) {
    unsigned long long u;
    asm("mov.b64 %0, {%1, %2};" : "=l"(u) : "f"(a), "f"(b));
    return u;
}
__device__ __forceinline__ void upk2(unsigned long long u, float& lo, float& hi) {
    asm("mov.b64 {%0, %1}, %2;" : "=f"(lo), "=f"(hi) : "l"(u));
}

// ============================================================
// Kernel 1: hp = h @ W + b ; s = (hp@a_src + b_attn)*log2e ; d = hp@a_dst*log2e
// 512 blocks x 128 threads; 32 rows/block; 4 threads per row x 16 cols each.
// ============================================================
__global__ __launch_bounds__(128) void k_proj(
    const float* __restrict__ h, const float* __restrict__ W,
    const float* __restrict__ bfc, const float* __restrict__ asrc,
    const float* __restrict__ adst, const float* __restrict__ battn) {
    __shared__ __align__(16) float sW[IND * OUTD];   // 32 KB
    __shared__ __align__(16) float sh[32 * IND];     // 16 KB
    __shared__ float sb[OUTD], sas[OUTD], sad[OUTD];
    const int tid = threadIdx.x;
    const int row0 = blockIdx.x * 32;

    for (int v = tid; v < IND * OUTD / 4; v += 128)
        ((float4*)sW)[v] = ((const float4*)W)[v];
    for (int v = tid; v < 32 * IND / 4; v += 128)
        ((float4*)sh)[v] = ((const float4*)(h + (size_t)row0 * IND))[v];
    if (tid < OUTD) { sb[tid] = bfc[tid]; sas[tid] = asrc[tid]; sad[tid] = adst[tid]; }
    __syncthreads();

    const int r = tid >> 2;      // local row 0..31
    const int cq = tid & 3;      // column quarter
    const int c0 = cq * 16;

    unsigned long long acc[8];
#pragma unroll
    for (int i = 0; i < 8; i++) acc[i] = pk2(sb[c0 + 2 * i], sb[c0 + 2 * i + 1]);

    const float4* hrow = (const float4*)(sh + r * IND);
#pragma unroll 4
    for (int k4 = 0; k4 < IND / 4; k4++) {
        float4 hv = hrow[k4];
        float hk[4] = {hv.x, hv.y, hv.z, hv.w};
#pragma unroll
        for (int kk = 0; kk < 4; kk++) {
            unsigned long long hh = pk2(hk[kk], hk[kk]);
            const ulonglong2* wrow = (const ulonglong2*)(sW + (k4 * 4 + kk) * OUTD + c0);
            ulonglong2 w01 = wrow[0], w23 = wrow[1], w45 = wrow[2], w67 = wrow[3];
            acc[0] = fma2(hh, w01.x, acc[0]); acc[1] = fma2(hh, w01.y, acc[1]);
            acc[2] = fma2(hh, w23.x, acc[2]); acc[3] = fma2(hh, w23.y, acc[3]);
            acc[4] = fma2(hh, w45.x, acc[4]); acc[5] = fma2(hh, w45.y, acc[5]);
            acc[6] = fma2(hh, w67.x, acc[6]); acc[7] = fma2(hh, w67.y, acc[7]);
        }
    }

    float o[16];
#pragma unroll
    for (int i = 0; i < 8; i++) upk2(acc[i], o[2 * i], o[2 * i + 1]);

    float s = 0.f, d = 0.f;
#pragma unroll
    for (int c = 0; c < 16; c++) {
        s = fmaf(o[c], sas[c0 + c], s);
        d = fmaf(o[c], sad[c0 + c], d);
    }
    // reduce over the 4 column-quarter lanes (cq lives in the low 2 lane bits)
    s += __shfl_xor_sync(0xffffffffu, s, 1);
    d += __shfl_xor_sync(0xffffffffu, d, 1);
    s += __shfl_xor_sync(0xffffffffu, s, 2);
    d += __shfl_xor_sync(0xffffffffu, d, 2);

    const int grow = row0 + r;
    if (cq == 0) {
        g_s[grow] = (s + battn[0]) * LOG2E;
        g_d[grow] = d * LOG2E;
    }
    float4* dst = (float4*)(g_hp + (size_t)grow * OUTD + c0);
#pragma unroll
    for (int q = 0; q < 4; q++)
        dst[q] = make_float4(o[4 * q], o[4 * q + 1], o[4 * q + 2], o[4 * q + 3]);
}

// ============================================================
// Kernel 2: per-batch max of prescaled d (8 blocks x 256 threads)
// ============================================================
__global__ void k_dmax() {
    __shared__ float sm[256];
    int b = blockIdx.x, tid = threadIdx.x;
    float m = -1e30f;
    for (int j = tid; j < NN; j += 256) m = fmaxf(m, g_d[b * NN + j]);
    sm[tid] = m;
    __syncthreads();
    for (int off = 128; off > 0; off >>= 1) {
        if (tid < off) sm[tid] = fmaxf(sm[tid], sm[tid + off]);
        __syncthreads();
    }
    if (tid == 0) g_dmax[b] = sm[0];
}

// ============================================================
// Kernel 3: fused scores -> leaky -> softmax -> attn@hp -> elu
// grid (N/64, B), 128 threads. hp tile register-prefetched so its
// LDGs overlap the previous tile's FFMA2 phase.
// ============================================================
__global__ __launch_bounds__(128) void k_attn(float* __restrict__ out) {
    __shared__ __align__(16) float s_hp[64 * 64];   // hp tile [j][c] (16 KB)
    __shared__ __align__(16) float s_w[64 * 64];    // weights [j][i] (16 KB)
    __shared__ float s_sum[128];

    const int b = blockIdx.y;
    const int i0 = blockIdx.x * 64;
    const int tid = threadIdx.x;

    const int iw = tid & 63;       // exp-phase row identity
    const int half = tid >> 6;     // exp-phase j-half
    const int ig = tid & 15;       // mma-phase 4-row group
    const int cg = tid >> 4;       // mma-phase 8-col group

    const float si = g_s[b * NN + i0 + iw];          // prescaled, incl. b_attn
    const float tmax = si + g_dmax[b];
    const float mi = fmaxf(tmax, NEG_SLOPE * tmax);  // exact row max (log2 units)

    const float* __restrict__ hpB = g_hp + (size_t)b * NN * OUTD;
    const float* __restrict__ dB = g_d + b * NN;

    unsigned long long acc[16];
#pragma unroll
    for (int i = 0; i < 16; i++) acc[i] = 0ull;
    float wsum = 0.f;

    // prefetch hp tile 0 into registers
    float4 pre[8];
#pragma unroll
    for (int v = 0; v < 8; v++) {
        int lin = v * 128 + tid;
        int row = lin >> 4, c4 = lin & 15;
        pre[v] = ((const float4*)(hpB + (size_t)row * OUTD))[c4];
    }

    for (int jt = 0; jt < NN / 64; jt++) {
        const int j0 = jt * 64;
        __syncthreads();  // previous tile's MMA fully consumed smem

        // stage prefetched hp tile
#pragma unroll
        for (int v = 0; v < 8; v++) {
            int lin = v * 128 + tid;
            int row = lin >> 4, c4 = lin & 15;
            ((float4*)s_hp)[row * 16 + c4] = pre[v];
        }

        // exp weights: thread owns (iw, j-half); d read as uniform float4 LDG
        const float4* dj = (const float4*)(dB + j0 + half * 32);
#pragma unroll
        for (int r4 = 0; r4 < 8; r4++) {
            float4 dv = dj[r4];
            float dd[4] = {dv.x, dv.y, dv.z, dv.w};
#pragma unroll
            for (int q = 0; q < 4; q++) {
                int j = half * 32 + r4 * 4 + q;
                float t = si + dd[q];
                float sc = fmaxf(t, NEG_SLOPE * t);   // leaky (log2 units)
                float w = exp2f(sc - mi);
                wsum += w;
                s_w[j * 64 + iw] = w;
            }
        }
        __syncthreads();

        // prefetch next hp tile; LDG latency hidden behind the MMA below
        if (jt + 1 < NN / 64) {
#pragma unroll
            for (int v = 0; v < 8; v++) {
                int lin = v * 128 + tid;
                int row = lin >> 4, c4 = lin & 15;
                pre[v] = ((const float4*)(hpB + (size_t)(j0 + 64 + row) * OUTD))[c4];
            }
        }

        // register-tiled (64x64)@(64x64) with packed f32x2 FMA
        const float* wp = s_w + ig * 4;
        const float* hq = s_hp + cg * 8;
#pragma unroll 8
        for (int j = 0; j < 64; j++) {
            float4 wv = *(const float4*)(wp + j * 64);
            ulonglong2 ha = *(const ulonglong2*)(hq + j * 64);
            ulonglong2 hb = *(const ulonglong2*)(hq + j * 64 + 4);
            float wa[4] = {wv.x, wv.y, wv.z, wv.w};
#pragma unroll
            for (int ii = 0; ii < 4; ii++) {
                unsigned long long ww = pk2(wa[ii], wa[ii]);
                acc[ii * 4 + 0] = fma2(ww, ha.x, acc[ii * 4 + 0]);
                acc[ii * 4 + 1] = fma2(ww, ha.y, acc[ii * 4 + 1]);
                acc[ii * 4 + 2] = fma2(ww, hb.x, acc[ii * 4 + 2]);
                acc[ii * 4 + 3] = fma2(ww, hb.y, acc[ii * 4 + 3]);
            }
        }
    }

    __syncthreads();
    s_sum[half * 64 + iw] = wsum;
    __syncthreads();

    // epilogue: normalize, elu, store
#pragma unroll
    for (int ii = 0; ii < 4; ii++) {
        int il = ig * 4 + ii;
        float inv = 1.0f / (s_sum[il] + s_sum[64 + il]);
        float o[8];
#pragma unroll
        for (int p = 0; p < 4; p++) upk2(acc[ii * 4 + p], o[2 * p], o[2 * p + 1]);
#pragma unroll
        for (int c = 0; c < 8; c++) {
            float v = o[c] * inv;
            o[c] = v > 0.f ? v : (__expf(v) - 1.0f);  // elu
        }
        float* dst = out + ((size_t)(b * NN + i0 + il)) * OUTD + cg * 8;
        *(float4*)dst = make_float4(o[0], o[1], o[2], o[3]);
        *(float4*)(dst + 4) = make_float4(o[4], o[5], o[6], o[7]);
    }
}

extern "C" void kernel_launch(void* const* d_in, const int* in_sizes, int n_in,
                              void* d_out, int out_size) {
    const float* h = (const float*)d_in[0];
    const float* W = (const float*)d_in[1];
    const float* bfc = (const float*)d_in[2];
    const float* asrc = (const float*)d_in[3];
    const float* adst = (const float*)d_in[4];
    const float* battn = (const float*)d_in[5];
    float* out = (float*)d_out;

    k_proj<<<BB * NN / 32, 128>>>(h, W, bfc, asrc, adst, battn);
    k_dmax<<<BB, 256>>>();
    k_attn<<<dim3(NN / 64, BB), 128>>>(out);
}

// round 8
// speedup vs baseline: 1.1496x; 1.1496x over previous
#include <cuda_runtime.h>
#include <cstdint>

// Problem constants
#define BB 8
#define NN 2048
#define IND 128
#define OUTD 64
#define NEG_SLOPE 0.2f
#define LOG2E 1.4426950408889634f

// Scratch (device globals: no allocation allowed)
__device__ float g_hp[BB * NN * OUTD];   // projected features (4 MB)
__device__ float g_s[BB * NN];           // (hp @ a_src + b_attn) * log2e
__device__ float g_d[BB * NN];           // (hp @ a_dst) * log2e
__device__ float g_dmax[BB];             // per-batch max of prescaled d

// ---------- packed f32x2 helpers ----------
__device__ __forceinline__ unsigned long long fma2(unsigned long long a,
                                                   unsigned long long b,
                                                   unsigned long long c) {
    unsigned long long d;
    asm("fma.rn.f32x2 %0, %1, %2, %3;" : "=l"(d) : "l"(a), "l"(b), "l"(c));
    return d;
}
__device__ __forceinline__ unsigned long long pk2(float a, float b) {
    unsigned long long u;
    asm("mov.b64 %0, {%1, %2};" : "=l"(u) : "f"(a), "f"(b));
    return u;
}
__device__ __forceinline__ void upk2(unsigned long long u, float& lo, float& hi) {
    asm("mov.b64 {%0, %1}, %2;" : "=f"(lo), "=f"(hi) : "l"(u));
}

// ============================================================
// Kernel 1: hp = h @ W + b ; s = (hp@a_src + b_attn)*log2e ; d = hp@a_dst*log2e
// 256 CTAs x 128 threads. 64 rows/CTA, 2 threads per row (split-K over
// IND=128). Each thread accumulates ALL 64 cols over its 64 k's; W reads
// from smem are 2-way-broadcast. Halves merged via shfl xor 1.
// ============================================================
__global__ __launch_bounds__(128) void k_proj(
    const float* __restrict__ h, const float* __restrict__ W,
    const float* __restrict__ bfc, const float* __restrict__ asrc,
    const float* __restrict__ adst, const float* __restrict__ battn) {
    __shared__ __align__(16) float sW[IND * OUTD];   // 32 KB
    __shared__ float sb[OUTD], sas[OUTD], sad[OUTD];
    const int tid = threadIdx.x;

    for (int v = tid; v < IND * OUTD / 4; v += 128)
        ((float4*)sW)[v] = ((const float4*)W)[v];
    if (tid < OUTD) { sb[tid] = bfc[tid]; sas[tid] = asrc[tid]; sad[tid] = adst[tid]; }
    __syncthreads();

    const int r = tid >> 1;            // local row 0..63
    const int kh = tid & 1;            // k-half
    const int row = blockIdx.x * 64 + r;

    unsigned long long acc[32];        // 64 output columns as 32 f32x2 pairs
    if (kh == 0) {
#pragma unroll
        for (int i = 0; i < 32; i++) acc[i] = pk2(sb[2 * i], sb[2 * i + 1]);
    } else {
#pragma unroll
        for (int i = 0; i < 32; i++) acc[i] = 0ull;
    }

    const float4* h4 = (const float4*)(h + (size_t)row * IND + kh * 64);
#pragma unroll 2
    for (int k4 = 0; k4 < 16; k4++) {
        float4 hv = h4[k4];
        float hk[4] = {hv.x, hv.y, hv.z, hv.w};
#pragma unroll
        for (int kk = 0; kk < 4; kk++) {
            int kg = kh * 64 + k4 * 4 + kk;
            unsigned long long hh = pk2(hk[kk], hk[kk]);
            const ulonglong2* wrow = (const ulonglong2*)(sW + kg * OUTD);
#pragma unroll
            for (int q = 0; q < 16; q++) {            // 16 x ulonglong2 = 64 floats
                ulonglong2 wv = wrow[q];
                acc[2 * q + 0] = fma2(hh, wv.x, acc[2 * q + 0]);
                acc[2 * q + 1] = fma2(hh, wv.y, acc[2 * q + 1]);
            }
        }
    }

    float o[64];
#pragma unroll
    for (int i = 0; i < 32; i++) upk2(acc[i], o[2 * i], o[2 * i + 1]);
    // merge the two k-halves (lane xor 1 = same row, other half)
#pragma unroll
    for (int c = 0; c < 64; c++) o[c] += __shfl_xor_sync(0xffffffffu, o[c], 1);

    // s/d: each half-thread covers 32 cols, then shfl-combine
    float s = 0.f, d = 0.f;
#pragma unroll
    for (int c = 0; c < 32; c++) {
        int cc = kh * 32 + c;
        s = fmaf(o[cc], sas[cc], s);
        d = fmaf(o[cc], sad[cc], d);
    }
    s += __shfl_xor_sync(0xffffffffu, s, 1);
    d += __shfl_xor_sync(0xffffffffu, d, 1);
    if (kh == 0) {
        g_s[row] = (s + battn[0]) * LOG2E;
        g_d[row] = d * LOG2E;
    }

    // store: kh==0 writes cols 0..31, kh==1 writes cols 32..63
    float4* dst = (float4*)(g_hp + (size_t)row * OUTD + kh * 32);
#pragma unroll
    for (int q = 0; q < 8; q++) {
        int c = kh * 32 + q * 4;
        dst[q] = make_float4(o[c], o[c + 1], o[c + 2], o[c + 3]);
    }
}

// ============================================================
// Kernel 2: per-batch max of prescaled d (8 blocks x 256 threads)
// ============================================================
__global__ void k_dmax() {
    __shared__ float sm[256];
    int b = blockIdx.x, tid = threadIdx.x;
    float m = -1e30f;
    for (int j = tid; j < NN; j += 256) m = fmaxf(m, g_d[b * NN + j]);
    sm[tid] = m;
    __syncthreads();
    for (int off = 128; off > 0; off >>= 1) {
        if (tid < off) sm[tid] = fmaxf(sm[tid], sm[tid + off]);
        __syncthreads();
    }
    if (tid == 0) g_dmax[b] = sm[0];
}

// ============================================================
// Kernel 3: fused scores -> leaky -> softmax -> attn@hp -> elu
// grid (N/32, B) = 512 CTAs x 128 threads. i-tile 32, j-tile 64.
// Thread MMA tile: 2 i-rows x 8 cols (acc as 8 f32x2 pairs).
// ============================================================
__global__ __launch_bounds__(128) void k_attn(float* __restrict__ out) {
    __shared__ __align__(16) float s_hp[64 * 64];   // hp tile [j][c] (16 KB)
    __shared__ __align__(16) float s_w[64 * 32];    // weights [j][i] (8 KB)
    __shared__ float s_sum[128];

    const int b = blockIdx.y;
    const int i0 = blockIdx.x * 32;
    const int tid = threadIdx.x;

    const int iw = tid & 31;       // exp-phase row identity (32 rows)
    const int half = tid >> 5;     // exp-phase j-quarter (4 x 16 j's)
    const int ig = tid & 15;       // mma-phase 2-row group
    const int cg = tid >> 4;       // mma-phase 8-col group

    const float si = g_s[b * NN + i0 + iw];          // prescaled, incl. b_attn
    const float tmax = si + g_dmax[b];
    const float mi = fmaxf(tmax, NEG_SLOPE * tmax);  // exact row max (log2 units)

    const float* __restrict__ hpB = g_hp + (size_t)b * NN * OUTD;
    const float* __restrict__ dB = g_d + b * NN;

    unsigned long long acc[8];
#pragma unroll
    for (int i = 0; i < 8; i++) acc[i] = 0ull;
    float wsum = 0.f;

    for (int jt = 0; jt < NN / 64; jt++) {
        const int j0 = jt * 64;
        __syncthreads();  // previous tile fully consumed

        // stage hp tile (64x64 f32) coalesced
#pragma unroll
        for (int v = 0; v < 8; v++) {
            int lin = v * 128 + tid;       // float4 index 0..1023
            int row = lin >> 4, c4 = lin & 15;
            ((float4*)s_hp)[row * 16 + c4] =
                ((const float4*)(hpB + (size_t)(j0 + row) * OUTD))[c4];
        }

        // exp weights: thread owns (iw, j-quarter of 16); d via uniform float4
        const float4* dj = (const float4*)(dB + j0 + half * 16);
#pragma unroll
        for (int r4 = 0; r4 < 4; r4++) {
            float4 dv = dj[r4];
            float dd[4] = {dv.x, dv.y, dv.z, dv.w};
#pragma unroll
            for (int q = 0; q < 4; q++) {
                int j = half * 16 + r4 * 4 + q;
                float t = si + dd[q];
                float sc = fmaxf(t, NEG_SLOPE * t);   // leaky (log2 units)
                float w = exp2f(sc - mi);
                wsum += w;
                s_w[j * 32 + iw] = w;
            }
        }
        __syncthreads();

        // register-tiled (32x64)@(64x64) slice with packed f32x2 FMA
        const float* wp = s_w + ig * 2;
        const float* hq = s_hp + cg * 8;
#pragma unroll 8
        for (int j = 0; j < 64; j++) {
            float2 wv = *(const float2*)(wp + j * 32);
            ulonglong2 ha = *(const ulonglong2*)(hq + j * 64);       // c0..c3
            ulonglong2 hb = *(const ulonglong2*)(hq + j * 64 + 4);   // c4..c7
            unsigned long long w0 = pk2(wv.x, wv.x);
            unsigned long long w1 = pk2(wv.y, wv.y);
            acc[0] = fma2(w0, ha.x, acc[0]);
            acc[1] = fma2(w0, ha.y, acc[1]);
            acc[2] = fma2(w0, hb.x, acc[2]);
            acc[3] = fma2(w0, hb.y, acc[3]);
            acc[4] = fma2(w1, ha.x, acc[4]);
            acc[5] = fma2(w1, ha.y, acc[5]);
            acc[6] = fma2(w1, hb.x, acc[6]);
            acc[7] = fma2(w1, hb.y, acc[7]);
        }
    }

    __syncthreads();
    s_sum[half * 32 + iw] = wsum;
    __syncthreads();

    // epilogue: normalize, elu, store (2 rows x 8 cols per thread)
#pragma unroll
    for (int ii = 0; ii < 2; ii++) {
        int il = ig * 2 + ii;
        float tot = s_sum[il] + s_sum[32 + il] + s_sum[64 + il] + s_sum[96 + il];
        float inv = 1.0f / tot;
        float o[8];
#pragma unroll
        for (int p = 0; p < 4; p++) upk2(acc[ii * 4 + p], o[2 * p], o[2 * p + 1]);
#pragma unroll
        for (int c = 0; c < 8; c++) {
            float v = o[c] * inv;
            o[c] = v > 0.f ? v : (__expf(v) - 1.0f);  // elu
        }
        float* dst = out + ((size_t)(b * NN + i0 + il)) * OUTD + cg * 8;
        *(float4*)dst = make_float4(o[0], o[1], o[2], o[3]);
        *(float4*)(dst + 4) = make_float4(o[4], o[5], o[6], o[7]);
    }
}

extern "C" void kernel_launch(void* const* d_in, const int* in_sizes, int n_in,
                              void* d_out, int out_size) {
    const float* h = (const float*)d_in[0];
    const float* W = (const float*)d_in[1];
    const float* bfc = (const float*)d_in[2];
    const float* asrc = (const float*)d_in[3];
    const float* adst = (const float*)d_in[4];
    const float* battn = (const float*)d_in[5];
    float* out = (float*)d_out;

    k_proj<<<BB * NN / 64, 128>>>(h, W, bfc, asrc, adst, battn);
    k_dmax<<<BB, 256>>>();
    k_attn<<<dim3(NN / 32, BB), 128>>>(out);
}

// round 11
// speedup vs baseline: 1.2594x; 1.0956x over previous
#include <cuda_runtime.h>
#include <cstdint>

// Problem constants
#define BB 8
#define NN 2048
#define IND 128
#define OUTD 64
#define NEG_SLOPE 0.2f
#define LOG2E 1.4426950408889634f

// Scratch (device globals: no allocation allowed)
__device__ float g_hp[BB * NN * OUTD];   // projected features (4 MB)
__device__ float g_s[BB * NN];           // (hp @ a_src + b_attn) * log2e
__device__ float g_d[BB * NN];           // (hp @ a_dst) * log2e
__device__ float g_dmax[BB];             // per-batch max of prescaled d

// ---------- packed f32x2 helpers ----------
__device__ __forceinline__ unsigned long long fma2(unsigned long long a,
                                                   unsigned long long b,
                                                   unsigned long long c) {
    unsigned long long d;
    asm("fma.rn.f32x2 %0, %1, %2, %3;" : "=l"(d) : "l"(a), "l"(b), "l"(c));
    return d;
}
__device__ __forceinline__ unsigned long long pk2(float a, float b) {
    unsigned long long u;
    asm("mov.b64 %0, {%1, %2};" : "=l"(u) : "f"(a), "f"(b));
    return u;
}
__device__ __forceinline__ void upk2(unsigned long long u, float& lo, float& hi) {
    asm("mov.b64 {%0, %1}, %2;" : "=f"(lo), "=f"(hi) : "l"(u));
}

// ---------- cp.async helpers ----------
__device__ __forceinline__ void cp16(uint32_t dst_smem, const void* src) {
    asm volatile("cp.async.cg.shared.global [%0], [%1], 16;"
                 :: "r"(dst_smem), "l"(src));
}
__device__ __forceinline__ void cp_commit() {
    asm volatile("cp.async.commit_group;");
}
__device__ __forceinline__ void cp_wait_all() {
    asm volatile("cp.async.wait_group 0;");
}

// ============================================================
// Kernel 1: hp = h @ W + b ; s = (hp@a_src + b_attn)*log2e ; d = hp@a_dst*log2e
// 128 CTAs x 128 threads (single wave), 1 row per thread; W in smem with
// warp-uniform (broadcast) reads; packed f32x2 FMA for the 64-col accumulate.
// ============================================================
__global__ __launch_bounds__(128) void k_proj(
    const float* __restrict__ h, const float* __restrict__ W,
    const float* __restrict__ bfc, const float* __restrict__ asrc,
    const float* __restrict__ adst, const float* __restrict__ battn) {
    __shared__ __align__(16) float sW[IND * OUTD];   // 32 KB
    __shared__ float sb[OUTD], sas[OUTD], sad[OUTD];
    const int tid = threadIdx.x;

    for (int v = tid; v < IND * OUTD / 4; v += 128)
        ((float4*)sW)[v] = ((const float4*)W)[v];
    if (tid < OUTD) { sb[tid] = bfc[tid]; sas[tid] = asrc[tid]; sad[tid] = adst[tid]; }
    __syncthreads();

    const int row = blockIdx.x * 128 + tid;   // 0..16383

    unsigned long long acc[32];               // 64 cols as 32 f32x2 pairs
#pragma unroll
    for (int i = 0; i < 32; i++) acc[i] = pk2(sb[2 * i], sb[2 * i + 1]);

    const float4* h4 = (const float4*)(h + (size_t)row * IND);
#pragma unroll 4
    for (int k4 = 0; k4 < IND / 4; k4++) {
        float4 hv = h4[k4];
        float hk[4] = {hv.x, hv.y, hv.z, hv.w};
#pragma unroll
        for (int kk = 0; kk < 4; kk++) {
            unsigned long long hh = pk2(hk[kk], hk[kk]);
            const ulonglong2* wrow = (const ulonglong2*)(sW + (k4 * 4 + kk) * OUTD);
#pragma unroll
            for (int q = 0; q < 16; q++) {    // 16 x ulonglong2 = 64 floats
                ulonglong2 wv = wrow[q];
                acc[2 * q + 0] = fma2(hh, wv.x, acc[2 * q + 0]);
                acc[2 * q + 1] = fma2(hh, wv.y, acc[2 * q + 1]);
            }
        }
    }

    float o[64];
#pragma unroll
    for (int i = 0; i < 32; i++) upk2(acc[i], o[2 * i], o[2 * i + 1]);

    float s = 0.f, d = 0.f;
#pragma unroll
    for (int c = 0; c < OUTD; c++) {
        s = fmaf(o[c], sas[c], s);
        d = fmaf(o[c], sad[c], d);
    }
    g_s[row] = (s + battn[0]) * LOG2E;
    g_d[row] = d * LOG2E;

    float4* dst = (float4*)(g_hp + (size_t)row * OUTD);
#pragma unroll
    for (int q = 0; q < 16; q++)
        dst[q] = make_float4(o[4 * q], o[4 * q + 1], o[4 * q + 2], o[4 * q + 3]);
}

// ============================================================
// Kernel 2: per-batch max of prescaled d (8 blocks x 256 threads)
// ============================================================
__global__ void k_dmax() {
    __shared__ float sm[256];
    int b = blockIdx.x, tid = threadIdx.x;
    float m = -1e30f;
    for (int j = tid; j < NN; j += 256) m = fmaxf(m, g_d[b * NN + j]);
    sm[tid] = m;
    __syncthreads();
    for (int off = 128; off > 0; off >>= 1) {
        if (tid < off) sm[tid] = fmaxf(sm[tid], sm[tid + off]);
        __syncthreads();
    }
    if (tid == 0) g_dmax[b] = sm[0];
}

// ============================================================
// Kernel 3: fused scores -> leaky -> softmax -> attn@hp -> elu
// grid (N/32, B) = 512 CTAs x 128 threads. i-tile 32, j-tile 64.
// hp tiles double-buffered in smem, filled by cp.async issued before
// the MMA phase so the load retires behind 64 j-iters of FFMA2.
// ============================================================
__global__ __launch_bounds__(128) void k_attn(float* __restrict__ out) {
    __shared__ __align__(16) float s_hp[2][64 * 64];  // 2 x 16 KB
    __shared__ __align__(16) float s_w[64 * 32];      // 8 KB
    __shared__ float s_sum[128];

    const int b = blockIdx.y;
    const int i0 = blockIdx.x * 32;
    const int tid = threadIdx.x;

    const int iw = tid & 31;       // exp-phase row identity (32 rows)
    const int half = tid >> 5;     // exp-phase j-quarter (4 x 16 j's)
    const int ig = tid & 15;       // mma-phase 2-row group
    const int cg = tid >> 4;       // mma-phase 8-col group

    const float si = g_s[b * NN + i0 + iw];          // prescaled, incl. b_attn
    const float tmax = si + g_dmax[b];
    const float mi = fmaxf(tmax, NEG_SLOPE * tmax);  // exact row max (log2 units)

    const float* __restrict__ hpB = g_hp + (size_t)b * NN * OUTD;
    const float* __restrict__ dB = g_d + b * NN;

    // per-thread staging slice: 8 x 16B chunks of the 64x64 tile
    const int st_row = tid >> 4;          // rows st_row, st_row+8, ..., st_row+56
    const int st_c4 = (tid & 15) * 4;     // float offset within row

    // issue cp.async for tile jt into buffer buf
    auto issue_tile = [&](int jt, int buf) {
        const float* src = hpB + (size_t)jt * 64 * OUTD;
        uint32_t dbase = (uint32_t)__cvta_generic_to_shared(
            &s_hp[buf][st_row * 64 + st_c4]);
#pragma unroll
        for (int v = 0; v < 8; v++) {
            cp16(dbase + v * 8 * 64 * 4,
                 src + (size_t)(st_row + v * 8) * OUTD + st_c4);
        }
        cp_commit();
    };

    unsigned long long acc[8];
#pragma unroll
    for (int i = 0; i < 8; i++) acc[i] = 0ull;
    float wsum = 0.f;

    issue_tile(0, 0);

    for (int jt = 0; jt < NN / 64; jt++) {
        const int j0 = jt * 64;
        const int buf = jt & 1;

        // exp weights: thread owns (iw, j-quarter of 16); d via uniform float4
        const float4* dj = (const float4*)(dB + j0 + half * 16);
#pragma unroll
        for (int r4 = 0; r4 < 4; r4++) {
            float4 dv = dj[r4];
            float dd[4] = {dv.x, dv.y, dv.z, dv.w};
#pragma unroll
            for (int q = 0; q < 4; q++) {
                int j = half * 16 + r4 * 4 + q;
                float t = si + dd[q];
                float sc = fmaxf(t, NEG_SLOPE * t);   // leaky (log2 units)
                float w = exp2f(sc - mi);
                wsum += w;
                s_w[j * 32 + iw] = w;
            }
        }
        cp_wait_all();          // this thread's hp chunks for tile jt landed
        __syncthreads();        // all threads' s_w writes + hp chunks visible

        // prefetch next tile into the other buffer; hides behind MMA below
        if (jt + 1 < NN / 64) issue_tile(jt + 1, buf ^ 1);

        // register-tiled (32x64)@(64x64) slice with packed f32x2 FMA
        const float* wp = s_w + ig * 2;
        const float* hq = s_hp[buf] + cg * 8;
#pragma unroll 8
        for (int j = 0; j < 64; j++) {
            float2 wv = *(const float2*)(wp + j * 32);
            ulonglong2 ha = *(const ulonglong2*)(hq + j * 64);       // c0..c3
            ulonglong2 hb = *(const ulonglong2*)(hq + j * 64 + 4);   // c4..c7
            unsigned long long w0 = pk2(wv.x, wv.x);
            unsigned long long w1 = pk2(wv.y, wv.y);
            acc[0] = fma2(w0, ha.x, acc[0]);
            acc[1] = fma2(w0, ha.y, acc[1]);
            acc[2] = fma2(w0, hb.x, acc[2]);
            acc[3] = fma2(w0, hb.y, acc[3]);
            acc[4] = fma2(w1, ha.x, acc[4]);
            acc[5] = fma2(w1, ha.y, acc[5]);
            acc[6] = fma2(w1, hb.x, acc[6]);
            acc[7] = fma2(w1, hb.y, acc[7]);
        }
        __syncthreads();        // MMA done before next exp overwrites s_w
    }

    s_sum[half * 32 + iw] = wsum;
    __syncthreads();

    // epilogue: normalize, elu, store (2 rows x 8 cols per thread)
#pragma unroll
    for (int ii = 0; ii < 2; ii++) {
        int il = ig * 2 + ii;
        float tot = s_sum[il] + s_sum[32 + il] + s_sum[64 + il] + s_sum[96 + il];
        float inv = 1.0f / tot;
        float o[8];
#pragma unroll
        for (int p = 0; p < 4; p++) upk2(acc[ii * 4 + p], o[2 * p], o[2 * p + 1]);
#pragma unroll
        for (int c = 0; c < 8; c++) {
            float v = o[c] * inv;
            o[c] = v > 0.f ? v : (__expf(v) - 1.0f);  // elu
        }
        float* dst = out + ((size_t)(b * NN + i0 + il)) * OUTD + cg * 8;
        *(float4*)dst = make_float4(o[0], o[1], o[2], o[3]);
        *(float4*)(dst + 4) = make_float4(o[4], o[5], o[6], o[7]);
    }
}

extern "C" void kernel_launch(void* const* d_in, const int* in_sizes, int n_in,
                              void* d_out, int out_size) {
    const float* h = (const float*)d_in[0];
    const float* W = (const float*)d_in[1];
    const float* bfc = (const float*)d_in[2];
    const float* asrc = (const float*)d_in[3];
    const float* adst = (const float*)d_in[4];
    const float* battn = (const float*)d_in[5];
    float* out = (float*)d_out;

    k_proj<<<BB * NN / 128, 128>>>(h, W, bfc, asrc, adst, battn);
    k_dmax<<<BB, 256>>>();
    k_attn<<<dim3(NN / 32, BB), 128>>>(out);
}